// round 8
// baseline (speedup 1.0000x reference)
#include <cuda_runtime.h>
#include <cstdint>

// CRF loss: inputs [1024,512,50] f32, transitions [50,50] f32,
// masks [1024,512] int32 (bool shipped as i32!), tag_indices [1024,512] i32.
// Output: [0] = loss scalar, [1..2500] = transitions passthrough.

#define BSZ 1024
#define SLEN 512
#define NC 50

__device__ float g_partial[BSZ];

__device__ __forceinline__ unsigned long long ffma2(unsigned long long a,
                                                    unsigned long long b,
                                                    unsigned long long c) {
    unsigned long long d;
    asm("fma.rn.f32x2 %0, %1, %2, %3;" : "=l"(d) : "l"(a), "l"(b), "l"(c));
    return d;
}
__device__ __forceinline__ unsigned long long fadd2(unsigned long long a,
                                                    unsigned long long b) {
    unsigned long long d;
    asm("add.rn.f32x2 %0, %1, %2;" : "=l"(d) : "l"(a), "l"(b));
    return d;
}
__device__ __forceinline__ unsigned long long pack2(float lo, float hi) {
    unsigned long long d;
    asm("mov.b64 %0, {%1, %2};" : "=l"(d) : "f"(lo), "f"(hi));
    return d;
}

__global__ void __launch_bounds__(32) crf_fwd_kernel(
    const float* __restrict__ x,        // [BSZ, SLEN, NC]
    const float* __restrict__ T,        // [NC, NC]
    const int* __restrict__ maskI,      // [BSZ, SLEN] int32 0/1
    const int* __restrict__ tags)       // [BSZ, SLEN]
{
    __shared__ float sT[NC * NC];
    __shared__ float2 pdup[2][64];      // duplicated p, double-buffered
    __shared__ int stags[SLEN];

    const int lane = threadIdx.x;
    const int b = blockIdx.x;
    const int c2 = 2 * lane;            // this lane owns states c2, c2+1
    const bool act = (lane < 25);       // 25 lanes cover 50 states

    // --- transitions -> shared (coalesced) ---
    for (int i = lane; i < NC * NC; i += 32) sT[i] = T[i];

    // --- len = 512 - sum(mask_int) (mask is monotone 0...0 1...1) ---
    const int4* mrow = reinterpret_cast<const int4*>(maskI + (size_t)b * SLEN);
    int msum = 0;
    #pragma unroll
    for (int k = 0; k < 4; ++k) {
        int4 v = mrow[lane + 32 * k];
        msum += v.x + v.y + v.z + v.w;
    }
    #pragma unroll
    for (int o = 16; o; o >>= 1)
        msum += __shfl_xor_sync(0xffffffffu, msum, o);
    const int len = SLEN - msum;        // in [128, 512]

    // --- tag row -> shared (coalesced) ---
    const int* trow = tags + (size_t)b * SLEN;
    for (int i = lane; i < len; i += 32) stags[i] = trow[i];
    __syncwarp();

    // --- E = exp(T) columns for this lane's two states, f32x2-packed ---
    unsigned long long Ecol[NC];
    #pragma unroll
    for (int c1 = 0; c1 < NC; ++c1) {
        float e0 = 0.f, e1 = 0.f;
        if (act) {
            e0 = __expf(sT[c1 * NC + c2]);
            e1 = __expf(sT[c1 * NC + c2 + 1]);
        }
        Ecol[c1] = pack2(e0, e1);
    }

    const float* xrow = x + (size_t)b * SLEN * NC;

    // --- unary + binary (separate pass, off the recurrence critical path) ---
    // unary:  sum_{t<len} x[b,t,tag[t]]
    // binary: sum_{1<=t<len} T[tag[t-1], tag[t]]
    float ub = 0.f;
    for (int t = lane; t < len; t += 32) {
        int tg = stags[t];
        ub += __ldg(xrow + (size_t)t * NC + tg);
        if (t > 0) ub += sT[stags[t - 1] * NC + tg];
    }
    #pragma unroll
    for (int o = 16; o; o >>= 1)
        ub += __shfl_xor_sync(0xffffffffu, ub, o);

    // --- forward recurrence over the unmasked prefix [0, len) ---
    float2 alpha = act ? *reinterpret_cast<const float2*>(xrow + c2)
                       : make_float2(-INFINITY, -INFINITY);

    float2 xn = make_float2(0.f, 0.f);
    if (act && len > 1)
        xn = *reinterpret_cast<const float2*>(xrow + NC + c2);

    int buf = 0;
    for (int t = 1; t < len; ++t) {
        float2 xc = xn;
        if (act && t + 1 < len)
            xn = *reinterpret_cast<const float2*>(xrow + (size_t)(t + 1) * NC + c2);

        // cheap shift: alpha[0] (cross-state spread is bounded by emission
        // spread + |T| << 88, so exp can't overflow; sp[0]=1 keeps s > 0)
        float m = __shfl_sync(0xffffffffu, alpha.x, 0);
        float p0 = __expf(alpha.x - m);   // inactive lanes: exp(-inf)=0, unused
        float p1 = __expf(alpha.y - m);
        if (act) {
            pdup[buf][c2]     = make_float2(p0, p0);
            pdup[buf][c2 + 1] = make_float2(p1, p1);
        }
        __syncwarp();

        // s[c2..c2+1] = sum_{c1} p[c1] * exp(T[c1][:]) ; packed f32x2
        const unsigned long long* pb =
            reinterpret_cast<const unsigned long long*>(pdup[buf]);
        unsigned long long a0 = 0ull, a1 = 0ull, a2 = 0ull, a3 = 0ull;
        #pragma unroll
        for (int c1 = 0; c1 < 48; c1 += 4) {
            a0 = ffma2(pb[c1],     Ecol[c1],     a0);
            a1 = ffma2(pb[c1 + 1], Ecol[c1 + 1], a1);
            a2 = ffma2(pb[c1 + 2], Ecol[c1 + 2], a2);
            a3 = ffma2(pb[c1 + 3], Ecol[c1 + 3], a3);
        }
        a0 = ffma2(pb[48], Ecol[48], a0);
        a1 = ffma2(pb[49], Ecol[49], a1);
        a0 = fadd2(a0, a2);
        a1 = fadd2(a1, a3);
        a0 = fadd2(a0, a1);
        float s0 = __uint_as_float((unsigned)(a0 & 0xffffffffull));
        float s1 = __uint_as_float((unsigned)(a0 >> 32));

        if (act) {
            alpha.x = xc.x + m + __logf(s0);
            alpha.y = xc.y + m + __logf(s1);
        }
        buf ^= 1;   // double buffer handles WAR across iterations
    }

    // --- final logsumexp over alpha (exact max shift) ---
    float mx = fmaxf(alpha.x, alpha.y);
    #pragma unroll
    for (int o = 16; o; o >>= 1)
        mx = fmaxf(mx, __shfl_xor_sync(0xffffffffu, mx, o));
    float es = __expf(alpha.x - mx) + __expf(alpha.y - mx); // -inf lanes -> 0
    #pragma unroll
    for (int o = 16; o; o >>= 1)
        es += __shfl_xor_sync(0xffffffffu, es, o);
    float log_norm = mx + __logf(es);

    if (lane == 0) g_partial[b] = ub - log_norm;
}

__global__ void crf_finalize_kernel(const float* __restrict__ T,
                                    float* __restrict__ out, int out_size) {
    __shared__ float red[256];
    int tid = threadIdx.x;
    float s = 0.f;
    for (int i = tid; i < BSZ; i += 256) s += g_partial[i];
    red[tid] = s;
    __syncthreads();
    #pragma unroll
    for (int o = 128; o; o >>= 1) {
        if (tid < o) red[tid] += red[tid + o];
        __syncthreads();
    }
    if (tid == 0) out[0] = -red[0] / (float)BSZ;
    // passthrough of transitions (second element of the reference tuple)
    if (out_size >= 1 + NC * NC) {
        for (int i = tid; i < NC * NC; i += 256) out[1 + i] = T[i];
    }
}

extern "C" void kernel_launch(void* const* d_in, const int* in_sizes, int n_in,
                              void* d_out, int out_size) {
    const float* x = (const float*)d_in[0];
    const float* T = (const float*)d_in[1];
    const int* maskI = (const int*)d_in[2];   // bool shipped as int32
    const int* tags = (const int*)d_in[3];
    float* out = (float*)d_out;
    (void)in_sizes; (void)n_in;

    crf_fwd_kernel<<<BSZ, 32>>>(x, T, maskI, tags);
    crf_finalize_kernel<<<1, 256>>>(T, out, out_size);
}

// round 9
// speedup vs baseline: 1.2100x; 1.2100x over previous
#include <cuda_runtime.h>
#include <cstdint>

// CRF loss: inputs [1024,512,50] f32, transitions [50,50] f32,
// masks [1024,512] int32 (bool shipped as i32), tag_indices [1024,512] i32.
// Output: [0] = loss scalar, [1..2500] = transitions passthrough.

#define BSZ 1024
#define SLEN 512
#define NC 50
#define LOG2E 1.4426950408889634f
#define LN2   0.6931471805599453f

__device__ float g_partial[BSZ];
__device__ unsigned int g_count = 0;

__device__ __forceinline__ unsigned long long ffma2(unsigned long long a,
                                                    unsigned long long b,
                                                    unsigned long long c) {
    unsigned long long d;
    asm("fma.rn.f32x2 %0, %1, %2, %3;" : "=l"(d) : "l"(a), "l"(b), "l"(c));
    return d;
}
__device__ __forceinline__ unsigned long long fadd2(unsigned long long a,
                                                    unsigned long long b) {
    unsigned long long d;
    asm("add.rn.f32x2 %0, %1, %2;" : "=l"(d) : "l"(a), "l"(b));
    return d;
}
__device__ __forceinline__ unsigned long long pack2(float lo, float hi) {
    unsigned long long d;
    asm("mov.b64 %0, {%1, %2};" : "=l"(d) : "f"(lo), "f"(hi));
    return d;
}
__device__ __forceinline__ void unpack2(float& lo, float& hi,
                                        unsigned long long v) {
    asm("mov.b64 {%0, %1}, %2;" : "=f"(lo), "=f"(hi) : "l"(v));
}
__device__ __forceinline__ float ex2f(float a) {
    float r; asm("ex2.approx.ftz.f32 %0, %1;" : "=f"(r) : "f"(a)); return r;
}
__device__ __forceinline__ float lg2f(float a) {
    float r; asm("lg2.approx.ftz.f32 %0, %1;" : "=f"(r) : "f"(a)); return r;
}

__global__ void __launch_bounds__(32) crf_fused_kernel(
    const float* __restrict__ x,      // [BSZ, SLEN, NC]
    const float* __restrict__ T,      // [NC, NC]
    const int* __restrict__ maskI,    // [BSZ, SLEN] int32 0/1
    const int* __restrict__ tags,     // [BSZ, SLEN]
    float* __restrict__ out, int out_size)
{
    __shared__ float sT[NC * NC];
    __shared__ ulonglong2 pdup[2][26];   // (p0,p0),(p1,p1) per active lane
    __shared__ int stags[SLEN];

    const int lane = threadIdx.x;
    const int b = blockIdx.x;
    const int c2 = 2 * lane;             // lane owns states c2, c2+1
    const bool act = (lane < 25);

    // --- stage T, mask-sum, tags ---
    for (int i = lane; i < NC * NC; i += 32) sT[i] = T[i];

    const int4* mrow = reinterpret_cast<const int4*>(maskI + (size_t)b * SLEN);
    int msum = 0;
    #pragma unroll
    for (int k = 0; k < 4; ++k) {
        int4 v = mrow[lane + 32 * k];
        msum += v.x + v.y + v.z + v.w;
    }
    #pragma unroll
    for (int o = 16; o; o >>= 1)
        msum += __shfl_xor_sync(0xffffffffu, msum, o);
    const int len = SLEN - msum;         // monotone mask => in [128, 512]

    const int* trow = tags + (size_t)b * SLEN;
    for (int i = lane; i < len; i += 32) stags[i] = trow[i];
    __syncwarp();

    // --- E = exp2(T * log2e) columns for this lane's two states ---
    unsigned long long Ecol[NC];
    #pragma unroll
    for (int c1 = 0; c1 < NC; ++c1) {
        float e0 = 0.f, e1 = 0.f;
        if (act) {
            e0 = ex2f(sT[c1 * NC + c2] * LOG2E);
            e1 = ex2f(sT[c1 * NC + c2 + 1] * LOG2E);
        }
        Ecol[c1] = pack2(e0, e1);
    }

    const float* xrow = x + (size_t)b * SLEN * NC;

    // --- unary + binary (natural domain, off the recurrence path) ---
    float ub = 0.f;
    for (int t = lane; t < len; t += 32) {
        int tg = stags[t];
        ub += __ldg(xrow + (size_t)t * NC + tg);
        if (t > 0) ub += sT[stags[t - 1] * NC + tg];
    }
    #pragma unroll
    for (int o = 16; o; o >>= 1)
        ub += __shfl_xor_sync(0xffffffffu, ub, o);

    // --- forward recurrence in log2 domain over [0, len) ---
    float2 x0 = act ? *reinterpret_cast<const float2*>(xrow + c2)
                    : make_float2(0.f, 0.f);
    float2 balpha = act ? make_float2(x0.x * LOG2E, x0.y * LOG2E)
                        : make_float2(-INFINITY, -INFINITY);

    float m = __shfl_sync(0xffffffffu, balpha.x, 0);  // exact for step 1

    float2 xn = make_float2(0.f, 0.f);                // len >= 128 > 1 always
    if (act)
        xn = *reinterpret_cast<const float2*>(xrow + NC + c2);

    ulonglong2* cur = pdup[0];
    ulonglong2* oth = pdup[1];

    for (int t = 1; t < len; ++t) {
        float2 xc = xn;
        if (act && t + 1 < len)
            xn = *reinterpret_cast<const float2*>(xrow + (size_t)(t + 1) * NC + c2);

        // p = exp2(balpha - m), m stale by one step (offset ~ one logZ
        // increment in log2 (~6.4) + bounded spread -> no overflow; the
        // stale shift is mathematically exact, range-wise safe)
        float p0 = ex2f(balpha.x - m);   // inactive lanes: exp2(-inf)=0, unused
        float p1 = ex2f(balpha.y - m);

        // broadcast CURRENT balpha[0] for NEXT step; latency hidden by matvec
        float mn = __shfl_sync(0xffffffffu, balpha.x, 0);

        if (act) {
            ulonglong2 w;
            w.x = pack2(p0, p0);
            w.y = pack2(p1, p1);
            cur[lane] = w;               // one STS.128
        }
        __syncwarp();

        // s[c2..c2+1] = sum_c1 p[c1] * E[c1][:], 25 LDS.128 + 50 FFMA2,
        // 8 accumulator chains (depth ~7)
        unsigned long long acc[8];
        #pragma unroll
        for (int i = 0; i < 8; ++i) acc[i] = 0ull;
        #pragma unroll
        for (int i = 0; i < 25; ++i) {
            ulonglong2 v = cur[i];
            acc[(2 * i) & 7]     = ffma2(v.x, Ecol[2 * i],     acc[(2 * i) & 7]);
            acc[(2 * i + 1) & 7] = ffma2(v.y, Ecol[2 * i + 1], acc[(2 * i + 1) & 7]);
        }
        unsigned long long r0 = fadd2(acc[0], acc[4]);
        unsigned long long r1 = fadd2(acc[1], acc[5]);
        unsigned long long r2 = fadd2(acc[2], acc[6]);
        unsigned long long r3 = fadd2(acc[3], acc[7]);
        r0 = fadd2(r0, r2);
        r1 = fadd2(r1, r3);
        r0 = fadd2(r0, r1);
        float s0, s1;
        unpack2(s0, s1, r0);

        if (act) {
            balpha.x = fmaf(xc.x, LOG2E, m + lg2f(s0));
            balpha.y = fmaf(xc.y, LOG2E, m + lg2f(s1));
        }
        m = mn;

        ulonglong2* tmp = cur; cur = oth; oth = tmp;  // WAR via double buffer
    }

    // --- final logsumexp (exact max shift, log2 domain) ---
    float mx = fmaxf(balpha.x, balpha.y);
    #pragma unroll
    for (int o = 16; o; o >>= 1)
        mx = fmaxf(mx, __shfl_xor_sync(0xffffffffu, mx, o));
    float es = ex2f(balpha.x - mx) + ex2f(balpha.y - mx);  // -inf lanes -> 0
    #pragma unroll
    for (int o = 16; o; o >>= 1)
        es += __shfl_xor_sync(0xffffffffu, es, o);
    float log_norm = LN2 * (mx + lg2f(es));

    if (lane == 0) g_partial[b] = ub - log_norm;

    // --- fused finalize: last block reduces and writes output ---
    __threadfence();
    unsigned int ticket = 0;
    if (lane == 0) ticket = atomicAdd(&g_count, 1u);
    ticket = __shfl_sync(0xffffffffu, ticket, 0);
    if (ticket == BSZ - 1) {
        __threadfence();
        float s = 0.f;
        for (int i = lane; i < BSZ; i += 32) s += g_partial[i];
        #pragma unroll
        for (int o = 16; o; o >>= 1)
            s += __shfl_xor_sync(0xffffffffu, s, o);
        if (lane == 0) out[0] = -s / (float)BSZ;
        if (out_size >= 1 + NC * NC) {
            for (int i = lane; i < NC * NC; i += 32) out[1 + i] = sT[i];
        }
        if (lane == 0) g_count = 0;   // reset for next graph replay
    }
}

extern "C" void kernel_launch(void* const* d_in, const int* in_sizes, int n_in,
                              void* d_out, int out_size) {
    const float* x = (const float*)d_in[0];
    const float* T = (const float*)d_in[1];
    const int* maskI = (const int*)d_in[2];   // bool shipped as int32
    const int* tags = (const int*)d_in[3];
    float* out = (float*)d_out;
    (void)in_sizes; (void)n_in;

    crf_fused_kernel<<<BSZ, 32>>>(x, T, maskI, tags, out, out_size);
}

// round 10
// speedup vs baseline: 1.3274x; 1.0970x over previous
#include <cuda_runtime.h>
#include <cstdint>

// CRF loss: inputs [1024,512,50] f32, transitions [50,50] f32,
// masks [1024,512] int32 (bool shipped as i32), tag_indices [1024,512] i32.
// Output: [0] = loss scalar, [1..2500] = transitions passthrough.

#define BSZ 1024
#define SLEN 512
#define NC 50
#define LOG2E 1.4426950408889634f
#define LN2   0.6931471805599453f

__device__ float g_partial[BSZ];
__device__ unsigned int g_count = 0;

__device__ __forceinline__ unsigned long long ffma2(unsigned long long a,
                                                    unsigned long long b,
                                                    unsigned long long c) {
    unsigned long long d;
    asm("fma.rn.f32x2 %0, %1, %2, %3;" : "=l"(d) : "l"(a), "l"(b), "l"(c));
    return d;
}
__device__ __forceinline__ unsigned long long fadd2(unsigned long long a,
                                                    unsigned long long b) {
    unsigned long long d;
    asm("add.rn.f32x2 %0, %1, %2;" : "=l"(d) : "l"(a), "l"(b));
    return d;
}
__device__ __forceinline__ unsigned long long pack2(float lo, float hi) {
    unsigned long long d;
    asm("mov.b64 %0, {%1, %2};" : "=l"(d) : "f"(lo), "f"(hi));
    return d;
}
__device__ __forceinline__ void unpack2(float& lo, float& hi,
                                        unsigned long long v) {
    asm("mov.b64 {%0, %1}, %2;" : "=f"(lo), "=f"(hi) : "l"(v));
}
__device__ __forceinline__ float ex2f(float a) {
    float r; asm("ex2.approx.ftz.f32 %0, %1;" : "=f"(r) : "f"(a)); return r;
}
__device__ __forceinline__ float lg2f(float a) {
    float r; asm("lg2.approx.ftz.f32 %0, %1;" : "=f"(r) : "f"(a)); return r;
}

// One CRF forward step in log2 domain. p stored as (p0,p1) pairs; each
// FFMA2 accumulator's halves hold even-c1 / odd-c1 partials of ONE state.
__device__ __forceinline__ void crf_step(
    float2 xc, float2& balpha, float& m,
    float2* __restrict__ cur,
    const unsigned long long* __restrict__ Ec0,
    const unsigned long long* __restrict__ Ec1,
    bool act, int lane)
{
    float p0 = ex2f(balpha.x - m);   // inactive lanes: ex2(-inf)=0, unused
    float p1 = ex2f(balpha.y - m);
    // broadcast current balpha[0] for NEXT step (stale shift is exact math;
    // one-step offset ~6.4 in log2 + bounded spread -> no overflow)
    float mn = __shfl_sync(0xffffffffu, balpha.x, 0);
    if (act) cur[lane] = make_float2(p0, p1);   // STS.64
    __syncwarp();

    const unsigned long long* pb =
        reinterpret_cast<const unsigned long long*>(cur);
    unsigned long long a0 = 0ull, a1 = 0ull, a2 = 0ull, a3 = 0ull;
    unsigned long long b0 = 0ull, b1 = 0ull, b2 = 0ull, b3 = 0ull;
    #pragma unroll
    for (int i = 0; i < 24; i += 4) {
        unsigned long long v0 = pb[i],     v1 = pb[i + 1];
        unsigned long long v2 = pb[i + 2], v3 = pb[i + 3];
        a0 = ffma2(v0, Ec0[i],     a0);
        b0 = ffma2(v0, Ec1[i],     b0);
        a1 = ffma2(v1, Ec0[i + 1], a1);
        b1 = ffma2(v1, Ec1[i + 1], b1);
        a2 = ffma2(v2, Ec0[i + 2], a2);
        b2 = ffma2(v2, Ec1[i + 2], b2);
        a3 = ffma2(v3, Ec0[i + 3], a3);
        b3 = ffma2(v3, Ec1[i + 3], b3);
    }
    {
        unsigned long long v = pb[24];
        a0 = ffma2(v, Ec0[24], a0);
        b0 = ffma2(v, Ec1[24], b0);
    }
    a0 = fadd2(a0, a2); a1 = fadd2(a1, a3); a0 = fadd2(a0, a1);
    b0 = fadd2(b0, b2); b1 = fadd2(b1, b3); b0 = fadd2(b0, b1);
    float sa0, sa1, sb0, sb1;
    unpack2(sa0, sa1, a0);
    unpack2(sb0, sb1, b0);
    float s0 = sa0 + sa1;   // state c2
    float s1 = sb0 + sb1;   // state c2+1

    if (act) {
        balpha.x = fmaf(xc.x, LOG2E, m + lg2f(s0));
        balpha.y = fmaf(xc.y, LOG2E, m + lg2f(s1));
    }
    m = mn;
}

__global__ void __launch_bounds__(32) crf_fused_kernel(
    const float* __restrict__ x,      // [BSZ, SLEN, NC]
    const float* __restrict__ T,      // [NC, NC]
    const int* __restrict__ maskI,    // [BSZ, SLEN] int32 0/1
    const int* __restrict__ tags,     // [BSZ, SLEN]
    float* __restrict__ out, int out_size)
{
    __shared__ float sT[NC * NC];
    __shared__ float2 sp[2][26];      // (p0,p1) per active lane, double-buffered
    __shared__ int stags[SLEN];

    const int lane = threadIdx.x;
    const int b = blockIdx.x;
    const int c2 = 2 * lane;          // lane owns states c2, c2+1
    const bool act = (lane < 25);

    // --- stage T, mask-sum, tags ---
    for (int i = lane; i < NC * NC; i += 32) sT[i] = T[i];

    const int4* mrow = reinterpret_cast<const int4*>(maskI + (size_t)b * SLEN);
    int msum = 0;
    #pragma unroll
    for (int k = 0; k < 4; ++k) {
        int4 v = mrow[lane + 32 * k];
        msum += v.x + v.y + v.z + v.w;
    }
    #pragma unroll
    for (int o = 16; o; o >>= 1)
        msum += __shfl_xor_sync(0xffffffffu, msum, o);
    const int len = SLEN - msum;      // monotone mask => in [128, 512]

    const int* trow = tags + (size_t)b * SLEN;
    for (int i = lane; i < len; i += 32) stags[i] = trow[i];
    __syncwarp();

    // --- E packed over c1-pairs: Ec0[i]=(E[2i][c2],E[2i+1][c2]), etc. ---
    unsigned long long Ec0[25], Ec1[25];
    #pragma unroll
    for (int i = 0; i < 25; ++i) {
        float e00 = 0.f, e01 = 0.f, e10 = 0.f, e11 = 0.f;
        if (act) {
            e00 = ex2f(sT[(2 * i) * NC + c2] * LOG2E);
            e01 = ex2f(sT[(2 * i + 1) * NC + c2] * LOG2E);
            e10 = ex2f(sT[(2 * i) * NC + c2 + 1] * LOG2E);
            e11 = ex2f(sT[(2 * i + 1) * NC + c2 + 1] * LOG2E);
        }
        Ec0[i] = pack2(e00, e01);
        Ec1[i] = pack2(e10, e11);
    }

    const float* xrow = x + (size_t)b * SLEN * NC;

    // --- unary + binary (off the recurrence critical path) ---
    float ub = 0.f;
    for (int t = lane; t < len; t += 32) {
        int tg = stags[t];
        ub += __ldg(xrow + (size_t)t * NC + tg);
        if (t > 0) ub += sT[stags[t - 1] * NC + tg];
    }
    #pragma unroll
    for (int o = 16; o; o >>= 1)
        ub += __shfl_xor_sync(0xffffffffu, ub, o);

    // --- forward recurrence, log2 domain, prefetch depth 4 ---
    float2 x0 = act ? *reinterpret_cast<const float2*>(xrow + c2)
                    : make_float2(0.f, 0.f);
    float2 balpha = act ? make_float2(x0.x * LOG2E, x0.y * LOG2E)
                        : make_float2(-INFINITY, -INFINITY);
    float m = __shfl_sync(0xffffffffu, balpha.x, 0);   // exact for step 1

    // prologue: len >= 128, so steps 1..4 always exist
    float2 x1 = make_float2(0.f, 0.f), x2 = x1, x3 = x1, x4 = x1;
    if (act) {
        x1 = *reinterpret_cast<const float2*>(xrow + 1 * NC + c2);
        x2 = *reinterpret_cast<const float2*>(xrow + 2 * NC + c2);
        x3 = *reinterpret_cast<const float2*>(xrow + 3 * NC + c2);
        x4 = *reinterpret_cast<const float2*>(xrow + 4 * NC + c2);
    }

    float2* cur = sp[0];
    float2* oth = sp[1];
    int t = 1;
    for (; t + 7 < len; t += 4) {
        // front-batched prefetch for steps t+4..t+7 (MLP=4)
        float2 n1 = make_float2(0.f, 0.f), n2 = n1, n3 = n1, n4 = n1;
        if (act) {
            const float* p = xrow + (size_t)(t + 4) * NC + c2;
            n1 = *reinterpret_cast<const float2*>(p);
            n2 = *reinterpret_cast<const float2*>(p + NC);
            n3 = *reinterpret_cast<const float2*>(p + 2 * NC);
            n4 = *reinterpret_cast<const float2*>(p + 3 * NC);
        }
        crf_step(x1, balpha, m, cur, Ec0, Ec1, act, lane);
        crf_step(x2, balpha, m, oth, Ec0, Ec1, act, lane);
        crf_step(x3, balpha, m, cur, Ec0, Ec1, act, lane);
        crf_step(x4, balpha, m, oth, Ec0, Ec1, act, lane);
        x1 = n1; x2 = n2; x3 = n3; x4 = n4;
    }
    // epilogue: 4 <= len - t <= 7 remaining; x1..x4 cover steps t..t+3
    crf_step(x1, balpha, m, cur, Ec0, Ec1, act, lane);
    crf_step(x2, balpha, m, oth, Ec0, Ec1, act, lane);
    crf_step(x3, balpha, m, cur, Ec0, Ec1, act, lane);
    crf_step(x4, balpha, m, oth, Ec0, Ec1, act, lane);
    float2* bufs[2] = {cur, oth};
    int parity = 0;
    for (int u = t + 4; u < len; ++u) {
        float2 xd = act ? *reinterpret_cast<const float2*>(
                              xrow + (size_t)u * NC + c2)
                        : make_float2(0.f, 0.f);
        crf_step(xd, balpha, m, bufs[parity], Ec0, Ec1, act, lane);
        parity ^= 1;
    }

    // --- final logsumexp (exact max shift, log2 domain) ---
    float mx = fmaxf(balpha.x, balpha.y);
    #pragma unroll
    for (int o = 16; o; o >>= 1)
        mx = fmaxf(mx, __shfl_xor_sync(0xffffffffu, mx, o));
    float es = ex2f(balpha.x - mx) + ex2f(balpha.y - mx);  // -inf lanes -> 0
    #pragma unroll
    for (int o = 16; o; o >>= 1)
        es += __shfl_xor_sync(0xffffffffu, es, o);
    float log_norm = LN2 * (mx + lg2f(es));

    if (lane == 0) g_partial[b] = ub - log_norm;

    // --- fused finalize: last block reduces and writes output ---
    __threadfence();
    unsigned int ticket = 0;
    if (lane == 0) ticket = atomicAdd(&g_count, 1u);
    ticket = __shfl_sync(0xffffffffu, ticket, 0);
    if (ticket == BSZ - 1) {
        __threadfence();
        float s = 0.f;
        for (int i = lane; i < BSZ; i += 32) s += g_partial[i];
        #pragma unroll
        for (int o = 16; o; o >>= 1)
            s += __shfl_xor_sync(0xffffffffu, s, o);
        if (lane == 0) out[0] = -s / (float)BSZ;
        if (out_size >= 1 + NC * NC) {
            for (int i = lane; i < NC * NC; i += 32) out[1 + i] = sT[i];
        }
        if (lane == 0) g_count = 0;   // reset for next graph replay
    }
}

extern "C" void kernel_launch(void* const* d_in, const int* in_sizes, int n_in,
                              void* d_out, int out_size) {
    const float* x = (const float*)d_in[0];
    const float* T = (const float*)d_in[1];
    const int* maskI = (const int*)d_in[2];   // bool shipped as int32
    const int* tags = (const int*)d_in[3];
    float* out = (float*)d_out;
    (void)in_sizes; (void)n_in;

    crf_fused_kernel<<<BSZ, 32>>>(x, T, maskI, tags, out, out_size);
}

// round 11
// speedup vs baseline: 1.6267x; 1.2255x over previous
#include <cuda_runtime.h>
#include <cstdint>

// CRF loss: inputs [1024,512,50] f32, transitions [50,50] f32,
// masks [1024,512] int32 (bool shipped as i32), tag_indices [1024,512] i32.
// Output: [0] = loss scalar, [1..2500] = transitions passthrough.
// Strategy: forward-backward split — warp 0 runs alpha 0..mid, warp 1 runs
// beta len-1..mid, logZ = lse(alpha_mid + beta_mid). Halves the serial chain
// and doubles resident warps.

#define BSZ 1024
#define SLEN 512
#define NC 50
#define LOG2E 1.4426950408889634f
#define LN2   0.6931471805599453f

__device__ float g_partial[BSZ];
__device__ unsigned int g_count = 0;

__device__ __forceinline__ unsigned long long ffma2(unsigned long long a,
                                                    unsigned long long b,
                                                    unsigned long long c) {
    unsigned long long d;
    asm("fma.rn.f32x2 %0, %1, %2, %3;" : "=l"(d) : "l"(a), "l"(b), "l"(c));
    return d;
}
__device__ __forceinline__ unsigned long long fadd2(unsigned long long a,
                                                    unsigned long long b) {
    unsigned long long d;
    asm("add.rn.f32x2 %0, %1, %2;" : "=l"(d) : "l"(a), "l"(b));
    return d;
}
__device__ __forceinline__ unsigned long long pack2(float lo, float hi) {
    unsigned long long d;
    asm("mov.b64 %0, {%1, %2};" : "=l"(d) : "f"(lo), "f"(hi));
    return d;
}
__device__ __forceinline__ void unpack2(float& lo, float& hi,
                                        unsigned long long v) {
    asm("mov.b64 {%0, %1}, %2;" : "=f"(lo), "=f"(hi) : "l"(v));
}
__device__ __forceinline__ float ex2f(float a) {
    float r; asm("ex2.approx.ftz.f32 %0, %1;" : "=f"(r) : "f"(a)); return r;
}
__device__ __forceinline__ float lg2f(float a) {
    float r; asm("lg2.approx.ftz.f32 %0, %1;" : "=f"(r) : "f"(a)); return r;
}

// Shared matvec core: s[c2], s[c2+1] = sum_c1 v[c1] * Eh[c1][c2 or c2+1].
// v is in cur[] as (v0,v1) pairs; E packed over c1-pairs per output state.
__device__ __forceinline__ void matvec50(
    const float2* __restrict__ cur,
    const unsigned long long* __restrict__ E0,
    const unsigned long long* __restrict__ E1,
    float& s0, float& s1)
{
    const unsigned long long* pb =
        reinterpret_cast<const unsigned long long*>(cur);
    unsigned long long a0 = 0ull, a1 = 0ull, a2 = 0ull, a3 = 0ull;
    unsigned long long b0 = 0ull, b1 = 0ull, b2 = 0ull, b3 = 0ull;
    #pragma unroll
    for (int i = 0; i < 24; i += 4) {
        unsigned long long v0 = pb[i],     v1 = pb[i + 1];
        unsigned long long v2 = pb[i + 2], v3 = pb[i + 3];
        a0 = ffma2(v0, E0[i],     a0);
        b0 = ffma2(v0, E1[i],     b0);
        a1 = ffma2(v1, E0[i + 1], a1);
        b1 = ffma2(v1, E1[i + 1], b1);
        a2 = ffma2(v2, E0[i + 2], a2);
        b2 = ffma2(v2, E1[i + 2], b2);
        a3 = ffma2(v3, E0[i + 3], a3);
        b3 = ffma2(v3, E1[i + 3], b3);
    }
    {
        unsigned long long v = pb[24];
        a0 = ffma2(v, E0[24], a0);
        b0 = ffma2(v, E1[24], b0);
    }
    a0 = fadd2(a0, a2); a1 = fadd2(a1, a3); a0 = fadd2(a0, a1);
    b0 = fadd2(b0, b2); b1 = fadd2(b1, b3); b0 = fadd2(b0, b1);
    float sa0, sa1, sb0, sb1;
    unpack2(sa0, sa1, a0);
    unpack2(sb0, sb1, b0);
    s0 = sa0 + sa1;
    s1 = sb0 + sb1;
}

// Forward step (log2 domain): balpha_t = bx_t + m + lg2(E^T exp2(balpha-m))
__device__ __forceinline__ void crf_fstep(
    float2 xc, float2& balpha, float& m, float2* __restrict__ cur,
    const unsigned long long* __restrict__ Ec0,
    const unsigned long long* __restrict__ Ec1, bool act, int lane)
{
    float p0 = ex2f(balpha.x - m);     // inactive lanes: ex2(-inf)=0, unused
    float p1 = ex2f(balpha.y - m);
    float mn = __shfl_sync(0xffffffffu, balpha.x, 0);  // stale shift, exact math
    if (act) cur[lane] = make_float2(p0, p1);
    __syncwarp();
    float s0, s1;
    matvec50(cur, Ec0, Ec1, s0, s1);
    if (act) {
        balpha.x = fmaf(xc.x, LOG2E, m + lg2f(s0));
        balpha.y = fmaf(xc.y, LOG2E, m + lg2f(s1));
    }
    m = mn;
}

// Backward step: bbeta_t = m + lg2(E * exp2(bx_{t+1}+bbeta_{t+1} - m))
__device__ __forceinline__ void crf_bstep(
    float2 xc /* x_{t+1} */, float2& bbeta, float& m, float2* __restrict__ cur,
    const unsigned long long* __restrict__ Er0,
    const unsigned long long* __restrict__ Er1, bool act, int lane)
{
    float w0 = fmaf(xc.x, LOG2E, bbeta.x);   // inactive: 0*LOG2E + -inf = -inf
    float w1 = fmaf(xc.y, LOG2E, bbeta.y);
    float v0 = ex2f(w0 - m);
    float v1 = ex2f(w1 - m);
    float mn = __shfl_sync(0xffffffffu, w0, 0);
    if (act) cur[lane] = make_float2(v0, v1);
    __syncwarp();
    float s0, s1;
    matvec50(cur, Er0, Er1, s0, s1);
    if (act) {
        bbeta.x = m + lg2f(s0);
        bbeta.y = m + lg2f(s1);
    }
    m = mn;
}

__global__ void __launch_bounds__(64) crf_fused_kernel(
    const float* __restrict__ x,      // [BSZ, SLEN, NC]
    const float* __restrict__ T,      // [NC, NC]
    const int* __restrict__ maskI,    // [BSZ, SLEN] int32 0/1
    const int* __restrict__ tags,     // [BSZ, SLEN]
    float* __restrict__ out, int out_size)
{
    __shared__ float sT[NC * NC];
    __shared__ float2 spf[2][26];     // forward p buffers
    __shared__ float2 spb[2][26];     // backward v buffers
    __shared__ int stags[SLEN];
    __shared__ float salpha[52], sbeta[52];
    __shared__ float subs[2];

    const int tid = threadIdx.x;
    const int wid = tid >> 5;
    const int lane = tid & 31;
    const int b = blockIdx.x;
    const int c2 = 2 * lane;          // lane owns states c2, c2+1
    const bool act = (lane < 25);

    // --- stage T and tags (both warps), len (per-warp redundant) ---
    for (int i = tid; i < NC * NC; i += 64) sT[i] = T[i];

    const int4* mrow = reinterpret_cast<const int4*>(maskI + (size_t)b * SLEN);
    int msum = 0;
    #pragma unroll
    for (int k = 0; k < 4; ++k) {
        int4 v = mrow[lane + 32 * k];
        msum += v.x + v.y + v.z + v.w;
    }
    #pragma unroll
    for (int o = 16; o; o >>= 1)
        msum += __shfl_xor_sync(0xffffffffu, msum, o);
    const int len = SLEN - msum;      // monotone mask => in [128, 512]
    const int mid = (len - 1) >> 1;   // forward steps: mid; backward: len-1-mid

    const int* trow = tags + (size_t)b * SLEN;
    for (int i = tid; i < len; i += 64) stags[i] = trow[i];
    __syncthreads();

    const float* xrow = x + (size_t)b * SLEN * NC;

    // --- unary + binary split across both warps ---
    float ub = 0.f;
    for (int t = tid; t < len; t += 64) {
        int tg = stags[t];
        ub += __ldg(xrow + (size_t)t * NC + tg);
        if (t > 0) ub += sT[stags[t - 1] * NC + tg];
    }
    #pragma unroll
    for (int o = 16; o; o >>= 1)
        ub += __shfl_xor_sync(0xffffffffu, ub, o);
    if (lane == 0) subs[wid] = ub;

    if (wid == 0) {
        // ===================== FORWARD: t = 1..mid =====================
        unsigned long long Ec0[25], Ec1[25];   // E columns c2, c2+1
        #pragma unroll
        for (int i = 0; i < 25; ++i) {
            float e00 = 0.f, e01 = 0.f, e10 = 0.f, e11 = 0.f;
            if (act) {
                e00 = ex2f(sT[(2 * i) * NC + c2] * LOG2E);
                e01 = ex2f(sT[(2 * i + 1) * NC + c2] * LOG2E);
                e10 = ex2f(sT[(2 * i) * NC + c2 + 1] * LOG2E);
                e11 = ex2f(sT[(2 * i + 1) * NC + c2 + 1] * LOG2E);
            }
            Ec0[i] = pack2(e00, e01);
            Ec1[i] = pack2(e10, e11);
        }

        float2 x0 = act ? *reinterpret_cast<const float2*>(xrow + c2)
                        : make_float2(0.f, 0.f);
        float2 balpha = act ? make_float2(x0.x * LOG2E, x0.y * LOG2E)
                            : make_float2(-INFINITY, -INFINITY);
        float m = __shfl_sync(0xffffffffu, balpha.x, 0);  // exact for step 1

        const int lenF = mid + 1;     // steps t in [1, lenF); lenF-1 >= 63
        float2 x1 = make_float2(0.f, 0.f), x2 = x1, x3 = x1, x4 = x1;
        if (act) {
            x1 = *reinterpret_cast<const float2*>(xrow + 1 * NC + c2);
            x2 = *reinterpret_cast<const float2*>(xrow + 2 * NC + c2);
            x3 = *reinterpret_cast<const float2*>(xrow + 3 * NC + c2);
            x4 = *reinterpret_cast<const float2*>(xrow + 4 * NC + c2);
        }
        float2* cur = spf[0];
        float2* oth = spf[1];
        int t = 1;
        for (; t + 7 < lenF; t += 4) {
            float2 n1 = make_float2(0.f, 0.f), n2 = n1, n3 = n1, n4 = n1;
            if (act) {
                const float* p = xrow + (size_t)(t + 4) * NC + c2;
                n1 = *reinterpret_cast<const float2*>(p);
                n2 = *reinterpret_cast<const float2*>(p + NC);
                n3 = *reinterpret_cast<const float2*>(p + 2 * NC);
                n4 = *reinterpret_cast<const float2*>(p + 3 * NC);
            }
            crf_fstep(x1, balpha, m, cur, Ec0, Ec1, act, lane);
            crf_fstep(x2, balpha, m, oth, Ec0, Ec1, act, lane);
            crf_fstep(x3, balpha, m, cur, Ec0, Ec1, act, lane);
            crf_fstep(x4, balpha, m, oth, Ec0, Ec1, act, lane);
            x1 = n1; x2 = n2; x3 = n3; x4 = n4;
        }
        crf_fstep(x1, balpha, m, cur, Ec0, Ec1, act, lane);
        crf_fstep(x2, balpha, m, oth, Ec0, Ec1, act, lane);
        crf_fstep(x3, balpha, m, cur, Ec0, Ec1, act, lane);
        crf_fstep(x4, balpha, m, oth, Ec0, Ec1, act, lane);
        float2* bufs[2] = {cur, oth};
        int parity = 0;
        for (int u = t + 4; u < lenF; ++u) {
            float2 xd = act ? *reinterpret_cast<const float2*>(
                                  xrow + (size_t)u * NC + c2)
                            : make_float2(0.f, 0.f);
            crf_fstep(xd, balpha, m, bufs[parity], Ec0, Ec1, act, lane);
            parity ^= 1;
        }
        if (act) {
            salpha[c2]     = balpha.x;
            salpha[c2 + 1] = balpha.y;
        }
    } else {
        // ============ BACKWARD: j = 0..NB-1, t = len-2-j, uses x[len-1-j] ====
        unsigned long long Er0[25], Er1[25];   // E rows c2, c2+1
        #pragma unroll
        for (int i = 0; i < 25; ++i) {
            float e00 = 0.f, e01 = 0.f, e10 = 0.f, e11 = 0.f;
            if (act) {
                e00 = ex2f(sT[c2 * NC + 2 * i] * LOG2E);
                e01 = ex2f(sT[c2 * NC + 2 * i + 1] * LOG2E);
                e10 = ex2f(sT[(c2 + 1) * NC + 2 * i] * LOG2E);
                e11 = ex2f(sT[(c2 + 1) * NC + 2 * i + 1] * LOG2E);
            }
            Er0[i] = pack2(e00, e01);
            Er1[i] = pack2(e10, e11);
        }

        float2 bbeta = act ? make_float2(0.f, 0.f)
                           : make_float2(-INFINITY, -INFINITY);
        const int NB = len - 1 - mid;  // >= 63
        const float* xbase = xrow + (size_t)(len - 1) * NC + c2;  // j=0 -> x[len-1]

        float2 x1 = make_float2(0.f, 0.f), x2 = x1, x3 = x1, x4 = x1;
        if (act) {
            x1 = *reinterpret_cast<const float2*>(xbase);
            x2 = *reinterpret_cast<const float2*>(xbase - NC);
            x3 = *reinterpret_cast<const float2*>(xbase - 2 * NC);
            x4 = *reinterpret_cast<const float2*>(xbase - 3 * NC);
        }
        // exact shift for first step: w[0] = bx_{len-1}[0] + 0
        float m = __shfl_sync(0xffffffffu, x1.x * LOG2E, 0);

        float2* cur = spb[0];
        float2* oth = spb[1];
        int j = 0;
        for (; j + 7 < NB; j += 4) {
            float2 n1 = make_float2(0.f, 0.f), n2 = n1, n3 = n1, n4 = n1;
            if (act) {
                const float* p = xbase - (size_t)(j + 4) * NC;
                n1 = *reinterpret_cast<const float2*>(p);
                n2 = *reinterpret_cast<const float2*>(p - NC);
                n3 = *reinterpret_cast<const float2*>(p - 2 * NC);
                n4 = *reinterpret_cast<const float2*>(p - 3 * NC);
            }
            crf_bstep(x1, bbeta, m, cur, Er0, Er1, act, lane);
            crf_bstep(x2, bbeta, m, oth, Er0, Er1, act, lane);
            crf_bstep(x3, bbeta, m, cur, Er0, Er1, act, lane);
            crf_bstep(x4, bbeta, m, oth, Er0, Er1, act, lane);
            x1 = n1; x2 = n2; x3 = n3; x4 = n4;
        }
        crf_bstep(x1, bbeta, m, cur, Er0, Er1, act, lane);
        crf_bstep(x2, bbeta, m, oth, Er0, Er1, act, lane);
        crf_bstep(x3, bbeta, m, cur, Er0, Er1, act, lane);
        crf_bstep(x4, bbeta, m, oth, Er0, Er1, act, lane);
        float2* bufs[2] = {cur, oth};
        int parity = 0;
        for (int u = j + 4; u < NB; ++u) {
            float2 xd = act ? *reinterpret_cast<const float2*>(
                                  xbase - (size_t)u * NC)
                            : make_float2(0.f, 0.f);
            crf_bstep(xd, bbeta, m, bufs[parity], Er0, Er1, act, lane);
            parity ^= 1;
        }
        if (act) {
            sbeta[c2]     = bbeta.x;
            sbeta[c2 + 1] = bbeta.y;
        }
    }
    __syncthreads();

    if (wid == 0) {
        // --- combine: logZ = lse_c(alpha_mid + beta_mid), log2 domain ---
        float g0 = act ? salpha[c2] + sbeta[c2] : -INFINITY;
        float g1 = act ? salpha[c2 + 1] + sbeta[c2 + 1] : -INFINITY;
        float mx = fmaxf(g0, g1);
        #pragma unroll
        for (int o = 16; o; o >>= 1)
            mx = fmaxf(mx, __shfl_xor_sync(0xffffffffu, mx, o));
        float es = ex2f(g0 - mx) + ex2f(g1 - mx);
        #pragma unroll
        for (int o = 16; o; o >>= 1)
            es += __shfl_xor_sync(0xffffffffu, es, o);
        float log_norm = LN2 * (mx + lg2f(es));

        if (lane == 0) g_partial[b] = subs[0] + subs[1] - log_norm;

        // --- fused finalize: last block reduces and writes output ---
        __threadfence();
        unsigned int ticket = 0;
        if (lane == 0) ticket = atomicAdd(&g_count, 1u);
        ticket = __shfl_sync(0xffffffffu, ticket, 0);
        if (ticket == BSZ - 1) {
            __threadfence();
            float s = 0.f;
            for (int i = lane; i < BSZ; i += 32) s += g_partial[i];
            #pragma unroll
            for (int o = 16; o; o >>= 1)
                s += __shfl_xor_sync(0xffffffffu, s, o);
            if (lane == 0) out[0] = -s / (float)BSZ;
            if (out_size >= 1 + NC * NC) {
                for (int i = lane; i < NC * NC; i += 32) out[1 + i] = sT[i];
            }
            if (lane == 0) g_count = 0;   // reset for next graph replay
        }
    }
}

extern "C" void kernel_launch(void* const* d_in, const int* in_sizes, int n_in,
                              void* d_out, int out_size) {
    const float* x = (const float*)d_in[0];
    const float* T = (const float*)d_in[1];
    const int* maskI = (const int*)d_in[2];   // bool shipped as int32
    const int* tags = (const int*)d_in[3];
    float* out = (float*)d_out;
    (void)in_sizes; (void)n_in;

    crf_fused_kernel<<<BSZ, 64>>>(x, T, maskI, tags, out, out_size);
}